// round 10
// baseline (speedup 1.0000x reference)
#include <cuda_runtime.h>

// Problem constants: N=50000 nodes, D=64, E=800000 edges.
#define MAX_NODES   50000
#define MAX_EDGES   800000
#define DIM         64
#define CAP         128          // per-node bucket capacity (expected max degree ~40)
#define CAP_B       32           // per-node e==3 bucket capacity (expected max ~12)
#define OVF_MAX     8192

// Device-global scratch (no allocations allowed).
__device__ float g_emb[MAX_NODES * DIM];
__device__ float g_twohop[MAX_NODES * DIM];
__device__ int   g_cnt[MAX_NODES];              // A counts
__device__ int   g_cntB[MAX_NODES + 2];         // B counts; [N]=ovfA ctr, [N+1]=ovfB ctr
__device__ int   g_eA[MAX_NODES * CAP];         // packed: (src<<1) | two
__device__ int   g_eB[MAX_NODES * CAP_B];       // src for e==3 edges
__device__ int   g_ovfA[OVF_MAX * 2];           // (packed, dst)
__device__ int   g_ovfB[OVF_MAX * 2];           // (src, dst)

__device__ __forceinline__ void red_add_v4(float* p, float4 v) {
    asm volatile("red.global.add.v4.f32 [%0], {%1, %2, %3, %4};"
                 :: "l"(p), "f"(v.x), "f"(v.y), "f"(v.z), "f"(v.w)
                 : "memory");
}

// K1: emb = elu(x*w) (float4 per thread) + direct bucket insertion per edge.
// Requires g_cnt/g_cntB zeroed beforehand (memset nodes).
__global__ void k_emb_bucket(const float4* __restrict__ x,
                             const float4* __restrict__ w,
                             const int* __restrict__ src,
                             const int* __restrict__ dst,
                             const int* __restrict__ ef,
                             int total4, int n_edges) {
    int i = blockIdx.x * blockDim.x + threadIdx.x;
    if (i < total4) {
        float4 xv = x[i];
        float4 wv = w[i & (DIM / 4 - 1)];
        float4 e; float a;
        a = xv.x * wv.x; e.x = (a > 0.0f) ? a : expm1f(a);
        a = xv.y * wv.y; e.y = (a > 0.0f) ? a : expm1f(a);
        a = xv.z * wv.z; e.z = (a > 0.0f) ? a : expm1f(a);
        a = xv.w * wv.w; e.w = (a > 0.0f) ? a : expm1f(a);
        reinterpret_cast<float4*>(g_emb)[i] = e;
    }
    if (i < n_edges) {
        int s = src[i], d = dst[i], t = ef[i];
        int two = (t == 0) | (t == 4) | (t == 5);
        int packed = (s << 1) | two;
        int slot = atomicAdd(&g_cnt[d], 1);
        if (slot < CAP) {
            g_eA[d * CAP + slot] = packed;
        } else {
            int o = atomicAdd(&g_cntB[MAX_NODES], 1);
            if (o < OVF_MAX) { g_ovfA[2 * o] = packed; g_ovfA[2 * o + 1] = d; }
        }
        if (t == 3) {
            int slotb = atomicAdd(&g_cntB[d], 1);
            if (slotb < CAP_B) {
                g_eB[d * CAP_B + slotb] = s;
            } else {
                int o = atomicAdd(&g_cntB[MAX_NODES + 1], 1);
                if (o < OVF_MAX) { g_ovfB[2 * o] = s; g_ovfB[2 * o + 1] = d; }
            }
        }
    }
}

// K2: pull two-hop. 16 lanes per node; list walked in int4 chunks for MLP=4.
__global__ void k_gather_twohop(int n_nodes) {
    int gid  = blockIdx.x * blockDim.x + threadIdx.x;
    int node = gid >> 4;
    if (node >= n_nodes) return;
    int lane = gid & 15;
    int cnt  = g_cnt[node];
    if (cnt > CAP) cnt = CAP;
    const int*  list  = g_eA + node * CAP;
    const int4* list4 = reinterpret_cast<const int4*>(list);
    const float* emb  = g_emb + lane * 4;

    float4 acc = make_float4(0.f, 0.f, 0.f, 0.f);
    int k = 0;
    for (; k + 4 <= cnt; k += 4) {
        int4 pk = list4[k >> 2];
        // 4 independent row loads
        float4 v0 = *reinterpret_cast<const float4*>(emb + (size_t)(pk.x >> 1) * DIM);
        float4 v1 = *reinterpret_cast<const float4*>(emb + (size_t)(pk.y >> 1) * DIM);
        float4 v2 = *reinterpret_cast<const float4*>(emb + (size_t)(pk.z >> 1) * DIM);
        float4 v3 = *reinterpret_cast<const float4*>(emb + (size_t)(pk.w >> 1) * DIM);
        float s0 = 1.0f + (float)(pk.x & 1);
        float s1 = 1.0f + (float)(pk.y & 1);
        float s2 = 1.0f + (float)(pk.z & 1);
        float s3 = 1.0f + (float)(pk.w & 1);
        acc.x += v0.x * s0 + v1.x * s1 + v2.x * s2 + v3.x * s3;
        acc.y += v0.y * s0 + v1.y * s1 + v2.y * s2 + v3.y * s3;
        acc.z += v0.z * s0 + v1.z * s1 + v2.z * s2 + v3.z * s3;
        acc.w += v0.w * s0 + v1.w * s1 + v2.w * s2 + v3.w * s3;
    }
    for (; k < cnt; k++) {
        int packed = list[k];
        float sc = 1.0f + (float)(packed & 1);
        float4 v = *reinterpret_cast<const float4*>(emb + (size_t)(packed >> 1) * DIM);
        acc.x += v.x * sc; acc.y += v.y * sc; acc.z += v.z * sc; acc.w += v.w * sc;
    }
    *reinterpret_cast<float4*>(g_twohop + (size_t)node * DIM + lane * 4) = acc;
}

// K3: overflow fixup for two-hop (normally zero work).
__global__ void k_ovf_twohop() {
    int n = g_cntB[MAX_NODES];
    if (n > OVF_MAX) n = OVF_MAX;
    int lane = threadIdx.x & 15;
    for (int j = (blockIdx.x * blockDim.x + threadIdx.x) >> 4; j < n;
         j += (gridDim.x * blockDim.x) >> 4) {
        int packed = g_ovfA[2 * j];
        int d      = g_ovfA[2 * j + 1];
        int s = packed >> 1;
        float scale = 1.0f + (float)(packed & 1);
        float4 v = *reinterpret_cast<const float4*>(g_emb + (size_t)s * DIM + lane * 4);
        v.x *= scale; v.y *= scale; v.z *= scale; v.w *= scale;
        red_add_v4(g_twohop + (size_t)d * DIM + lane * 4, v);
    }
}

// K4: pull one-hop from dedicated e==3 buckets.
// First 4 entries loaded as one int4 (covers ~86% of nodes fully); scalar tail.
__global__ void k_gather_onehop(float* __restrict__ out, int n_nodes) {
    int gid  = blockIdx.x * blockDim.x + threadIdx.x;
    int node = gid >> 4;
    if (node >= n_nodes) return;
    int lane = gid & 15;
    int cnt  = g_cntB[node];
    if (cnt > CAP_B) cnt = CAP_B;
    const int* list = g_eB + node * CAP_B;
    const float* th = g_twohop + lane * 4;

    float4 acc = make_float4(0.f, 0.f, 0.f, 0.f);
    if (cnt > 0) {
        int4 pk = *reinterpret_cast<const int4*>(list);   // one LDG.128, 4 entries
        {
            float4 v = *reinterpret_cast<const float4*>(th + (size_t)pk.x * DIM);
            acc.x += v.x; acc.y += v.y; acc.z += v.z; acc.w += v.w;
        }
        if (cnt > 1) {
            float4 v = *reinterpret_cast<const float4*>(th + (size_t)pk.y * DIM);
            acc.x += v.x; acc.y += v.y; acc.z += v.z; acc.w += v.w;
        }
        if (cnt > 2) {
            float4 v = *reinterpret_cast<const float4*>(th + (size_t)pk.z * DIM);
            acc.x += v.x; acc.y += v.y; acc.z += v.z; acc.w += v.w;
        }
        if (cnt > 3) {
            float4 v = *reinterpret_cast<const float4*>(th + (size_t)pk.w * DIM);
            acc.x += v.x; acc.y += v.y; acc.z += v.z; acc.w += v.w;
        }
        for (int k = 4; k < cnt; k++) {
            float4 v = *reinterpret_cast<const float4*>(th + (size_t)list[k] * DIM);
            acc.x += v.x; acc.y += v.y; acc.z += v.z; acc.w += v.w;
        }
    }
    *reinterpret_cast<float4*>(out + (size_t)node * DIM + lane * 4) = acc;
}

// K5: overflow fixup for one-hop (normally zero work).
__global__ void k_ovf_onehop(float* __restrict__ out) {
    int n = g_cntB[MAX_NODES + 1];
    if (n > OVF_MAX) n = OVF_MAX;
    int lane = threadIdx.x & 15;
    for (int j = (blockIdx.x * blockDim.x + threadIdx.x) >> 4; j < n;
         j += (gridDim.x * blockDim.x) >> 4) {
        int s = g_ovfB[2 * j];
        int d = g_ovfB[2 * j + 1];
        float4 v = *reinterpret_cast<const float4*>(g_twohop + (size_t)s * DIM + lane * 4);
        red_add_v4(out + (size_t)d * DIM + lane * 4, v);
    }
}

extern "C" void kernel_launch(void* const* d_in, const int* in_sizes, int n_in,
                              void* d_out, int out_size) {
    const float* x   = (const float*)d_in[0];   // graph_embedding [N, D]
    const float* w   = (const float*)d_in[1];   // weight [1, D]
    const int*   src = (const int*)d_in[2];     // [E]
    const int*   dst = (const int*)d_in[3];     // [E]
    const int*   ef  = (const int*)d_in[4];     // [E]
    float* out = (float*)d_out;                 // [N, D]

    int total   = in_sizes[0];                  // N * D
    int n_edges = in_sizes[2];                  // E
    int n_nodes = total / DIM;
    int total4  = total / 4;

    const int T = 256;

    // Zero counters via memset nodes.
    void* p = nullptr;
    cudaGetSymbolAddress(&p, g_cnt);
    cudaMemsetAsync(p, 0, MAX_NODES * sizeof(int));
    cudaGetSymbolAddress(&p, g_cntB);
    cudaMemsetAsync(p, 0, (MAX_NODES + 2) * sizeof(int));

    // K1: emb + direct bucket insertion (A + B buckets)
    {
        int work = (total4 > n_edges) ? total4 : n_edges;
        k_emb_bucket<<<(work + T - 1) / T, T>>>((const float4*)x, (const float4*)w,
                                                src, dst, ef, total4, n_edges);
    }
    // K2: two-hop gather (16 lanes per node, chunked list)
    {
        int threads = n_nodes * 16;
        k_gather_twohop<<<(threads + T - 1) / T, T>>>(n_nodes);
    }
    // K3: overflow fixup (usually empty)
    k_ovf_twohop<<<4, T>>>();
    // K4: one-hop gather from B buckets
    {
        int threads = n_nodes * 16;
        k_gather_onehop<<<(threads + T - 1) / T, T>>>(out, n_nodes);
    }
    // K5: overflow fixup for one-hop (usually empty)
    k_ovf_onehop<<<4, T>>>(out);
}

// round 11
// speedup vs baseline: 1.3788x; 1.3788x over previous
#include <cuda_runtime.h>

// Problem constants: N=50000 nodes, E=800000 edges, D=64.
#define MAX_NODES   50000
#define MAX_EDGES   800000
#define DIM         64
#define CAP         128          // per-node bucket capacity (expected max degree ~40)
#define CAP_B       32           // per-node e==3 bucket capacity (expected max ~12)
#define OVF_MAX     8192

// Device-global scratch (no allocations allowed).
__device__ float g_emb[MAX_NODES * DIM];
__device__ float g_twohop[MAX_NODES * DIM];
__device__ int   g_cnt[MAX_NODES];              // A counts
__device__ int   g_cntB[MAX_NODES + 2];         // B counts; [N]=ovfA ctr, [N+1]=ovfB ctr
__device__ int   g_eA[MAX_NODES * CAP];         // packed: (src<<1) | two
__device__ int   g_eB[MAX_NODES * CAP_B];       // src for e==3 edges
__device__ int   g_ovfA[OVF_MAX * 2];           // (packed, dst)
__device__ int   g_ovfB[OVF_MAX * 2];           // (src, dst)

__device__ __forceinline__ void red_add_v4(float* p, float4 v) {
    asm volatile("red.global.add.v4.f32 [%0], {%1, %2, %3, %4};"
                 :: "l"(p), "f"(v.x), "f"(v.y), "f"(v.z), "f"(v.w)
                 : "memory");
}

// K1: emb = elu(x*w) (float4 per thread) + direct bucket insertion per edge.
// Requires g_cnt/g_cntB zeroed beforehand (memset nodes).
__global__ void k_emb_bucket(const float4* __restrict__ x,
                             const float4* __restrict__ w,
                             const int* __restrict__ src,
                             const int* __restrict__ dst,
                             const int* __restrict__ ef,
                             int total4, int n_edges) {
    int i = blockIdx.x * blockDim.x + threadIdx.x;
    if (i < total4) {
        float4 xv = x[i];
        float4 wv = w[i & (DIM / 4 - 1)];
        float4 e; float a;
        a = xv.x * wv.x; e.x = (a > 0.0f) ? a : expm1f(a);
        a = xv.y * wv.y; e.y = (a > 0.0f) ? a : expm1f(a);
        a = xv.z * wv.z; e.z = (a > 0.0f) ? a : expm1f(a);
        a = xv.w * wv.w; e.w = (a > 0.0f) ? a : expm1f(a);
        reinterpret_cast<float4*>(g_emb)[i] = e;
    }
    if (i < n_edges) {
        int s = src[i], d = dst[i], t = ef[i];
        int two = (t == 0) | (t == 4) | (t == 5);
        int packed = (s << 1) | two;
        int slot = atomicAdd(&g_cnt[d], 1);
        if (slot < CAP) {
            g_eA[d * CAP + slot] = packed;
        } else {
            int o = atomicAdd(&g_cntB[MAX_NODES], 1);
            if (o < OVF_MAX) { g_ovfA[2 * o] = packed; g_ovfA[2 * o + 1] = d; }
        }
        if (t == 3) {
            int slotb = atomicAdd(&g_cntB[d], 1);
            if (slotb < CAP_B) {
                g_eB[d * CAP_B + slotb] = s;
            } else {
                int o = atomicAdd(&g_cntB[MAX_NODES + 1], 1);
                if (o < OVF_MAX) { g_ovfB[2 * o] = s; g_ovfB[2 * o + 1] = d; }
            }
        }
    }
}

// K2: pull two-hop. 16 lanes per node, scalar list walk (R8 form — best measured).
__global__ void k_gather_twohop(int n_nodes) {
    int gid  = blockIdx.x * blockDim.x + threadIdx.x;
    int node = gid >> 4;
    if (node >= n_nodes) return;
    int lane = gid & 15;
    int cnt  = g_cnt[node];
    if (cnt > CAP) cnt = CAP;
    const int* list = g_eA + node * CAP;
    float4 acc = make_float4(0.f, 0.f, 0.f, 0.f);
    #pragma unroll 4
    for (int k = 0; k < cnt; k++) {
        int packed = list[k];
        float scale = 1.0f + (float)(packed & 1);
        int s = packed >> 1;
        float4 v = *reinterpret_cast<const float4*>(g_emb + (size_t)s * DIM + lane * 4);
        acc.x += v.x * scale; acc.y += v.y * scale;
        acc.z += v.z * scale; acc.w += v.w * scale;
    }
    *reinterpret_cast<float4*>(g_twohop + (size_t)node * DIM + lane * 4) = acc;
}

// K3: overflow fixup for two-hop (normally zero work).
__global__ void k_ovf_twohop() {
    int n = g_cntB[MAX_NODES];
    if (n > OVF_MAX) n = OVF_MAX;
    int lane = threadIdx.x & 15;
    for (int j = (blockIdx.x * blockDim.x + threadIdx.x) >> 4; j < n;
         j += (gridDim.x * blockDim.x) >> 4) {
        int packed = g_ovfA[2 * j];
        int d      = g_ovfA[2 * j + 1];
        int s = packed >> 1;
        float scale = 1.0f + (float)(packed & 1);
        float4 v = *reinterpret_cast<const float4*>(g_emb + (size_t)s * DIM + lane * 4);
        v.x *= scale; v.y *= scale; v.z *= scale; v.w *= scale;
        red_add_v4(g_twohop + (size_t)d * DIM + lane * 4, v);
    }
}

// K4: pull one-hop from dedicated e==3 buckets.
// Speculative int4 first-load issued in parallel with the count load:
// removes one serial L2 trip from the per-node dependency chain.
__global__ void k_gather_onehop(float* __restrict__ out, int n_nodes) {
    int gid  = blockIdx.x * blockDim.x + threadIdx.x;
    int node = gid >> 4;
    if (node >= n_nodes) return;
    int lane = gid & 15;
    const int* list = g_eB + node * CAP_B;
    const float* th = g_twohop + lane * 4;

    // Two independent loads — issued together, latencies overlap.
    int4 pk = *reinterpret_cast<const int4*>(list);   // speculative (always in-bounds)
    int cnt = g_cntB[node];
    if (cnt > CAP_B) cnt = CAP_B;

    float4 acc = make_float4(0.f, 0.f, 0.f, 0.f);
    if (cnt > 0) {
        float4 v = *reinterpret_cast<const float4*>(th + (size_t)pk.x * DIM);
        acc.x += v.x; acc.y += v.y; acc.z += v.z; acc.w += v.w;
    }
    if (cnt > 1) {
        float4 v = *reinterpret_cast<const float4*>(th + (size_t)pk.y * DIM);
        acc.x += v.x; acc.y += v.y; acc.z += v.z; acc.w += v.w;
    }
    if (cnt > 2) {
        float4 v = *reinterpret_cast<const float4*>(th + (size_t)pk.z * DIM);
        acc.x += v.x; acc.y += v.y; acc.z += v.z; acc.w += v.w;
    }
    if (cnt > 3) {
        float4 v = *reinterpret_cast<const float4*>(th + (size_t)pk.w * DIM);
        acc.x += v.x; acc.y += v.y; acc.z += v.z; acc.w += v.w;
    }
    for (int k = 4; k < cnt; k++) {
        float4 v = *reinterpret_cast<const float4*>(th + (size_t)list[k] * DIM);
        acc.x += v.x; acc.y += v.y; acc.z += v.z; acc.w += v.w;
    }
    *reinterpret_cast<float4*>(out + (size_t)node * DIM + lane * 4) = acc;
}

// K5: overflow fixup for one-hop (normally zero work).
__global__ void k_ovf_onehop(float* __restrict__ out) {
    int n = g_cntB[MAX_NODES + 1];
    if (n > OVF_MAX) n = OVF_MAX;
    int lane = threadIdx.x & 15;
    for (int j = (blockIdx.x * blockDim.x + threadIdx.x) >> 4; j < n;
         j += (gridDim.x * blockDim.x) >> 4) {
        int s = g_ovfB[2 * j];
        int d = g_ovfB[2 * j + 1];
        float4 v = *reinterpret_cast<const float4*>(g_twohop + (size_t)s * DIM + lane * 4);
        red_add_v4(out + (size_t)d * DIM + lane * 4, v);
    }
}

extern "C" void kernel_launch(void* const* d_in, const int* in_sizes, int n_in,
                              void* d_out, int out_size) {
    const float* x   = (const float*)d_in[0];   // graph_embedding [N, D]
    const float* w   = (const float*)d_in[1];   // weight [1, D]
    const int*   src = (const int*)d_in[2];     // [E]
    const int*   dst = (const int*)d_in[3];     // [E]
    const int*   ef  = (const int*)d_in[4];     // [E]
    float* out = (float*)d_out;                 // [N, D]

    int total   = in_sizes[0];                  // N * D
    int n_edges = in_sizes[2];                  // E
    int n_nodes = total / DIM;
    int total4  = total / 4;

    const int T = 256;

    // Zero counters via memset nodes.
    void* p = nullptr;
    cudaGetSymbolAddress(&p, g_cnt);
    cudaMemsetAsync(p, 0, MAX_NODES * sizeof(int));
    cudaGetSymbolAddress(&p, g_cntB);
    cudaMemsetAsync(p, 0, (MAX_NODES + 2) * sizeof(int));

    // K1: emb + direct bucket insertion (A + B buckets)
    {
        int work = (total4 > n_edges) ? total4 : n_edges;
        k_emb_bucket<<<(work + T - 1) / T, T>>>((const float4*)x, (const float4*)w,
                                                src, dst, ef, total4, n_edges);
    }
    // K2: two-hop gather (16 lanes per node)
    {
        int threads = n_nodes * 16;
        k_gather_twohop<<<(threads + T - 1) / T, T>>>(n_nodes);
    }
    // K3: overflow fixup (usually empty)
    k_ovf_twohop<<<4, T>>>();
    // K4: one-hop gather from B buckets
    {
        int threads = n_nodes * 16;
        k_gather_onehop<<<(threads + T - 1) / T, T>>>(out, n_nodes);
    }
    // K5: overflow fixup for one-hop (usually empty)
    k_ovf_onehop<<<4, T>>>(out);
}

// round 12
// speedup vs baseline: 1.3797x; 1.0007x over previous
#include <cuda_runtime.h>

// Problem constants: N=50000 nodes, E=800000 edges, D=64.
#define MAX_NODES   50000
#define MAX_EDGES   800000
#define DIM         64
#define CAP         64           // per-node bucket capacity (expected max degree ~40)
#define CAP_B       16           // per-node e==3 bucket capacity (expected max ~12)
#define OVF_MAX     8192

// Device-global scratch (no allocations allowed).
__device__ float g_emb[MAX_NODES * DIM];
__device__ float g_twohop[MAX_NODES * DIM];
__device__ int   g_cnt[MAX_NODES];              // A counts
__device__ int   g_cntB[MAX_NODES + 2];         // B counts; [N]=ovfA ctr, [N+1]=ovfB ctr
__device__ int   g_eA[MAX_NODES * CAP];         // packed: (src<<1) | two
__device__ int   g_eB[MAX_NODES * CAP_B];       // src for e==3 edges
__device__ int   g_ovfA[OVF_MAX * 2];           // (packed, dst)
__device__ int   g_ovfB[OVF_MAX * 2];           // (src, dst)

__device__ __forceinline__ void red_add_v4(float* p, float4 v) {
    asm volatile("red.global.add.v4.f32 [%0], {%1, %2, %3, %4};"
                 :: "l"(p), "f"(v.x), "f"(v.y), "f"(v.z), "f"(v.w)
                 : "memory");
}

// K1: emb = elu(x*w) (float4 per thread) + direct bucket insertion per edge.
// Requires g_cnt/g_cntB zeroed beforehand (memset nodes).
__global__ void k_emb_bucket(const float4* __restrict__ x,
                             const float4* __restrict__ w,
                             const int* __restrict__ src,
                             const int* __restrict__ dst,
                             const int* __restrict__ ef,
                             int total4, int n_edges) {
    int i = blockIdx.x * blockDim.x + threadIdx.x;
    if (i < total4) {
        float4 xv = x[i];
        float4 wv = w[i & (DIM / 4 - 1)];
        float4 e; float a;
        a = xv.x * wv.x; e.x = (a > 0.0f) ? a : expm1f(a);
        a = xv.y * wv.y; e.y = (a > 0.0f) ? a : expm1f(a);
        a = xv.z * wv.z; e.z = (a > 0.0f) ? a : expm1f(a);
        a = xv.w * wv.w; e.w = (a > 0.0f) ? a : expm1f(a);
        reinterpret_cast<float4*>(g_emb)[i] = e;
    }
    if (i < n_edges) {
        int s = src[i], d = dst[i], t = ef[i];
        int two = (t == 0) | (t == 4) | (t == 5);
        int packed = (s << 1) | two;
        int slot = atomicAdd(&g_cnt[d], 1);
        if (slot < CAP) {
            g_eA[d * CAP + slot] = packed;
        } else {
            int o = atomicAdd(&g_cntB[MAX_NODES], 1);
            if (o < OVF_MAX) { g_ovfA[2 * o] = packed; g_ovfA[2 * o + 1] = d; }
        }
        if (t == 3) {
            int slotb = atomicAdd(&g_cntB[d], 1);
            if (slotb < CAP_B) {
                g_eB[d * CAP_B + slotb] = s;
            } else {
                int o = atomicAdd(&g_cntB[MAX_NODES + 1], 1);
                if (o < OVF_MAX) { g_ovfB[2 * o] = s; g_ovfB[2 * o + 1] = d; }
            }
        }
    }
}

// K2: pull two-hop. 16 lanes per node, scalar list walk.
__global__ void k_gather_twohop(int n_nodes) {
    int gid  = blockIdx.x * blockDim.x + threadIdx.x;
    int node = gid >> 4;
    if (node >= n_nodes) return;
    int lane = gid & 15;
    int cnt  = g_cnt[node];
    if (cnt > CAP) cnt = CAP;
    const int* list = g_eA + node * CAP;
    float4 acc = make_float4(0.f, 0.f, 0.f, 0.f);
    #pragma unroll 4
    for (int k = 0; k < cnt; k++) {
        int packed = list[k];
        float scale = 1.0f + (float)(packed & 1);
        int s = packed >> 1;
        float4 v = *reinterpret_cast<const float4*>(g_emb + (size_t)s * DIM + lane * 4);
        acc.x += v.x * scale; acc.y += v.y * scale;
        acc.z += v.z * scale; acc.w += v.w * scale;
    }
    *reinterpret_cast<float4*>(g_twohop + (size_t)node * DIM + lane * 4) = acc;
}

// K3: overflow fixup for two-hop (normally zero work).
__global__ void k_ovf_twohop() {
    int n = g_cntB[MAX_NODES];
    if (n > OVF_MAX) n = OVF_MAX;
    int lane = threadIdx.x & 15;
    for (int j = (blockIdx.x * blockDim.x + threadIdx.x) >> 4; j < n;
         j += (gridDim.x * blockDim.x) >> 4) {
        int packed = g_ovfA[2 * j];
        int d      = g_ovfA[2 * j + 1];
        int s = packed >> 1;
        float scale = 1.0f + (float)(packed & 1);
        float4 v = *reinterpret_cast<const float4*>(g_emb + (size_t)s * DIM + lane * 4);
        v.x *= scale; v.y *= scale; v.z *= scale; v.w *= scale;
        red_add_v4(g_twohop + (size_t)d * DIM + lane * 4, v);
    }
}

// K4: pull one-hop from dedicated e==3 buckets.
// Speculative int4 first-load in parallel with the count load; streaming store
// for out (written once, never re-read by us) keeps L2 for hot data.
__global__ void k_gather_onehop(float* __restrict__ out, int n_nodes) {
    int gid  = blockIdx.x * blockDim.x + threadIdx.x;
    int node = gid >> 4;
    if (node >= n_nodes) return;
    int lane = gid & 15;
    const int* list = g_eB + node * CAP_B;
    const float* th = g_twohop + lane * 4;

    // Two independent loads — issued together, latencies overlap.
    int4 pk = *reinterpret_cast<const int4*>(list);   // speculative (always in-bounds)
    int cnt = g_cntB[node];
    if (cnt > CAP_B) cnt = CAP_B;

    float4 acc = make_float4(0.f, 0.f, 0.f, 0.f);
    if (cnt > 0) {
        float4 v = *reinterpret_cast<const float4*>(th + (size_t)pk.x * DIM);
        acc.x += v.x; acc.y += v.y; acc.z += v.z; acc.w += v.w;
    }
    if (cnt > 1) {
        float4 v = *reinterpret_cast<const float4*>(th + (size_t)pk.y * DIM);
        acc.x += v.x; acc.y += v.y; acc.z += v.z; acc.w += v.w;
    }
    if (cnt > 2) {
        float4 v = *reinterpret_cast<const float4*>(th + (size_t)pk.z * DIM);
        acc.x += v.x; acc.y += v.y; acc.z += v.z; acc.w += v.w;
    }
    if (cnt > 3) {
        float4 v = *reinterpret_cast<const float4*>(th + (size_t)pk.w * DIM);
        acc.x += v.x; acc.y += v.y; acc.z += v.z; acc.w += v.w;
    }
    for (int k = 4; k < cnt; k++) {
        float4 v = *reinterpret_cast<const float4*>(th + (size_t)list[k] * DIM);
        acc.x += v.x; acc.y += v.y; acc.z += v.z; acc.w += v.w;
    }
    __stcs(reinterpret_cast<float4*>(out + (size_t)node * DIM + lane * 4), acc);
}

// K5: overflow fixup for one-hop (normally zero work).
__global__ void k_ovf_onehop(float* __restrict__ out) {
    int n = g_cntB[MAX_NODES + 1];
    if (n > OVF_MAX) n = OVF_MAX;
    int lane = threadIdx.x & 15;
    for (int j = (blockIdx.x * blockDim.x + threadIdx.x) >> 4; j < n;
         j += (gridDim.x * blockDim.x) >> 4) {
        int s = g_ovfB[2 * j];
        int d = g_ovfB[2 * j + 1];
        float4 v = *reinterpret_cast<const float4*>(g_twohop + (size_t)s * DIM + lane * 4);
        red_add_v4(out + (size_t)d * DIM + lane * 4, v);
    }
}

extern "C" void kernel_launch(void* const* d_in, const int* in_sizes, int n_in,
                              void* d_out, int out_size) {
    const float* x   = (const float*)d_in[0];   // graph_embedding [N, D]
    const float* w   = (const float*)d_in[1];   // weight [1, D]
    const int*   src = (const int*)d_in[2];     // [E]
    const int*   dst = (const int*)d_in[3];     // [E]
    const int*   ef  = (const int*)d_in[4];     // [E]
    float* out = (float*)d_out;                 // [N, D]

    int total   = in_sizes[0];                  // N * D
    int n_edges = in_sizes[2];                  // E
    int n_nodes = total / DIM;
    int total4  = total / 4;

    const int T = 256;

    // Zero counters via memset nodes.
    void* p = nullptr;
    cudaGetSymbolAddress(&p, g_cnt);
    cudaMemsetAsync(p, 0, MAX_NODES * sizeof(int));
    cudaGetSymbolAddress(&p, g_cntB);
    cudaMemsetAsync(p, 0, (MAX_NODES + 2) * sizeof(int));

    // K1: emb + direct bucket insertion (A + B buckets)
    {
        int work = (total4 > n_edges) ? total4 : n_edges;
        k_emb_bucket<<<(work + T - 1) / T, T>>>((const float4*)x, (const float4*)w,
                                                src, dst, ef, total4, n_edges);
    }
    // K2: two-hop gather (16 lanes per node)
    {
        int threads = n_nodes * 16;
        k_gather_twohop<<<(threads + T - 1) / T, T>>>(n_nodes);
    }
    // K3: overflow fixup (usually empty)
    k_ovf_twohop<<<4, T>>>();
    // K4: one-hop gather from B buckets
    {
        int threads = n_nodes * 16;
        k_gather_onehop<<<(threads + T - 1) / T, T>>>(out, n_nodes);
    }
    // K5: overflow fixup for one-hop (usually empty)
    k_ovf_onehop<<<4, T>>>(out);
}